// round 15
// baseline (speedup 1.0000x reference)
#include <cuda_runtime.h>

// Shared memory layout (float indices).
// SHC: double-buffered h, paired layout: addr(k,b) = buf*1024 + (k>>1)*16 + b*2 + (k&1)
//      k 0..63: h1 (layer0 out), k 64..127: h2 (layer1 out)
#define SHC   0        // 2048 floats (2 buffers)
#define SGT0  2048     // layer0 gates, tid-indexed [256][8] with float4-swap swizzle
#define SGT1  4096     // layer1 gates
#define SX    6144     // x tile [512][8]
#define SMEM_FLOATS 10240   // 40 KB

typedef unsigned long long u64;

__device__ __forceinline__ float ftanh(float v) {
    float y;
    asm("tanh.approx.f32 %0, %1;" : "=f"(y) : "f"(v));
    return y;
}
__device__ __forceinline__ float fsig(float v) {
    return fmaf(ftanh(0.5f * v), 0.5f, 0.5f);
}
__device__ __forceinline__ u64 packf2(float lo, float hi) {
    u64 r;
    asm("mov.b64 %0, {%1, %2};" : "=l"(r)
        : "r"(__float_as_uint(lo)), "r"(__float_as_uint(hi)));
    return r;
}
__device__ __forceinline__ float2 unpackf2(u64 v) {
    unsigned int lo, hi;
    asm("mov.b64 {%0, %1}, %2;" : "=r"(lo), "=r"(hi) : "l"(v));
    return make_float2(__uint_as_float(lo), __uint_as_float(hi));
}
// d(lo,hi) += a(lo,hi) * b(lo,hi)   — packed dual-FMA (Blackwell f32x2)
__device__ __forceinline__ void ffma2(u64& d, u64 a, u64 b) {
    asm("fma.rn.f32x2 %0, %1, %2, %0;" : "+l"(d) : "l"(a), "l"(b));
}

__global__ void __launch_bounds__(256, 1)
lstm2_kernel(const float* __restrict__ x,
             const float* __restrict__ Wih0, const float* __restrict__ Whh0,
             const float* __restrict__ bih0, const float* __restrict__ bhh0,
             const float* __restrict__ Wih1, const float* __restrict__ Whh1,
             const float* __restrict__ bih1, const float* __restrict__ bhh1,
             const float* __restrict__ Wfc,  const float* __restrict__ bfc,
             float* __restrict__ out)
{
    extern __shared__ float sm[];
    const int tid  = threadIdx.x;
    const int l    = tid & 31;           // lane
    const int w    = tid >> 5;           // warp (0..7)
    const int gate = l & 3;              // i,f,g,o
    const int u    = l >> 2;             // unit-within-warp (0..7)
    const int jown = 8 * w + u;          // hidden unit of this thread's gate row
    const int r    = gate * 64 + jown;   // torch gate-row index
    const int swap4 = (u & 1) * 4;       // float4-swap swizzle for gate storage
    const int b0   = blockIdx.x * 8;     // batch base for this CTA

    const float wx_g    = Wih0[r];                       // [4H, I=1]
    const float bias0_g = bih0[r] + bhh0[r];
    const u64   init1   = packf2(bih1[r] + bhh1[r], 0.f);

    // ---- Persistent weights in registers (k-pair packed), row r ----
    u64 w0p[32];   // Whh0 row r   (multiplies h1_{t-1}, layer0)
    u64 w1p[32];   // Wih1 row r   (multiplies h1_t, layer1)
    u64 w2p[32];   // Whh1 row r   (multiplies h2_{t-1}, layer1)
    {
        const u64* p0 = (const u64*)(Whh0 + r * 64);
        const u64* pi = (const u64*)(Wih1 + r * 64);
        const u64* ph = (const u64*)(Whh1 + r * 64);
        #pragma unroll
        for (int q = 0; q < 32; ++q) w0p[q] = p0[q];
        #pragma unroll
        for (int q = 0; q < 32; ++q) w1p[q] = pi[q];
        #pragma unroll
        for (int q = 0; q < 32; ++q) w2p[q] = ph[q];
    }

    // ---- x tile: [t][b] layout ----
    for (int idx = tid; idx < 4096; idx += 256) {
        int t = idx >> 3, b = idx & 7;
        sm[SX + idx] = x[(b0 + b) * 512 + t];
    }
    // ---- Zero both h buffers ----
    for (int idx = tid; idx < 2048; idx += 256) sm[SHC + idx] = 0.f;
    __syncthreads();

    // ---- Update-phase assignment: lane updates unit jup = 8w + (l>>2), batches 2p,2p+1 ----
    const int uu   = u;                  // same split as gate ownership group
    const int p    = gate;               // reuse low bits: p in 0..3
    const int jup  = 8 * w + uu;
    const int pofs = (2 * p) ^ ((uu & 1) * 4);   // position of batch 2p in source slot
    const int gsrc = (w * 32 + uu * 4) * 8;      // base of the 4 gate rows for unit jup
    const int hoff1 = (jup >> 1) * 16 + 4 * p + (jup & 1);        // h1 slot, batch 2p
    const int hoff2 = 512 + (jup >> 1) * 16 + 4 * p + (jup & 1);  // h2 slot
    float c0a = 0.f, c0b = 0.f, c1a = 0.f, c1b = 0.f;             // cell states in regs

    // Pipelined loop: iter s computes L0 gates for t=s and L1 gates for t=s-1,
    // sharing the h1 broadcast loads. h read from buf[s&1], written to buf[(s+1)&1].
    for (int s = 0; s <= 512; ++s) {
        const bool doL0 = (s < 512);
        const bool doL1 = (s > 0);
        const float* hbase = &sm[SHC + (s & 1) * 1024];
        float*       hdst  = &sm[SHC + ((s + 1) & 1) * 1024];

        // ===== Merged gate phase =====
        {
            const float4* xr = (const float4*)&sm[SX + (s & 511) * 8];
            float4 xa = xr[0], xb = xr[1];
            u64 a0 = packf2(fmaf(wx_g, xa.x, bias0_g), 0.f);
            u64 a1 = packf2(fmaf(wx_g, xa.y, bias0_g), 0.f);
            u64 a2 = packf2(fmaf(wx_g, xa.z, bias0_g), 0.f);
            u64 a3 = packf2(fmaf(wx_g, xa.w, bias0_g), 0.f);
            u64 a4 = packf2(fmaf(wx_g, xb.x, bias0_g), 0.f);
            u64 a5 = packf2(fmaf(wx_g, xb.y, bias0_g), 0.f);
            u64 a6 = packf2(fmaf(wx_g, xb.z, bias0_g), 0.f);
            u64 a7 = packf2(fmaf(wx_g, xb.w, bias0_g), 0.f);
            u64 q0 = init1, q1 = init1, q2 = init1, q3 = init1;
            u64 q4 = init1, q5 = init1, q6 = init1, q7 = init1;

            // h1 pairs: each broadcast load feeds BOTH layers (1 LDS : 4 ffma2)
            #pragma unroll
            for (int jj = 0; jj < 32; ++jj) {
                const ulonglong2* hp = (const ulonglong2*)&hbase[jj * 16];
                u64 w0 = w0p[jj], w1 = w1p[jj];
                ulonglong2 h01 = hp[0];
                ffma2(a0, w0, h01.x); ffma2(q0, w1, h01.x);
                ffma2(a1, w0, h01.y); ffma2(q1, w1, h01.y);
                ulonglong2 h23 = hp[1];
                ffma2(a2, w0, h23.x); ffma2(q2, w1, h23.x);
                ffma2(a3, w0, h23.y); ffma2(q3, w1, h23.y);
                ulonglong2 h45 = hp[2];
                ffma2(a4, w0, h45.x); ffma2(q4, w1, h45.x);
                ffma2(a5, w0, h45.y); ffma2(q5, w1, h45.y);
                ulonglong2 h67 = hp[3];
                ffma2(a6, w0, h67.x); ffma2(q6, w1, h67.x);
                ffma2(a7, w0, h67.y); ffma2(q7, w1, h67.y);
            }
            // h2 pairs: layer1 recurrent half
            #pragma unroll
            for (int jj = 0; jj < 32; ++jj) {
                const ulonglong2* hp = (const ulonglong2*)&hbase[512 + jj * 16];
                u64 w2 = w2p[jj];
                ulonglong2 h01 = hp[0];
                ffma2(q0, w2, h01.x); ffma2(q1, w2, h01.y);
                ulonglong2 h23 = hp[1];
                ffma2(q2, w2, h23.x); ffma2(q3, w2, h23.y);
                ulonglong2 h45 = hp[2];
                ffma2(q4, w2, h45.x); ffma2(q5, w2, h45.y);
                ulonglong2 h67 = hp[3];
                ffma2(q6, w2, h67.x); ffma2(q7, w2, h67.y);
            }
            if (doL0) {
                float2 p0 = unpackf2(a0), p1 = unpackf2(a1), p2 = unpackf2(a2), p3 = unpackf2(a3);
                float2 p4 = unpackf2(a4), p5 = unpackf2(a5), p6 = unpackf2(a6), p7 = unpackf2(a7);
                float* gb = &sm[SGT0 + tid * 8];
                *(float4*)(gb + swap4)       = make_float4(p0.x + p0.y, p1.x + p1.y, p2.x + p2.y, p3.x + p3.y);
                *(float4*)(gb + (4 ^ swap4)) = make_float4(p4.x + p4.y, p5.x + p5.y, p6.x + p6.y, p7.x + p7.y);
            }
            if (doL1) {
                float2 p0 = unpackf2(q0), p1 = unpackf2(q1), p2 = unpackf2(q2), p3 = unpackf2(q3);
                float2 p4 = unpackf2(q4), p5 = unpackf2(q5), p6 = unpackf2(q6), p7 = unpackf2(q7);
                float* gb = &sm[SGT1 + tid * 8];
                *(float4*)(gb + swap4)       = make_float4(p0.x + p0.y, p1.x + p1.y, p2.x + p2.y, p3.x + p3.y);
                *(float4*)(gb + (4 ^ swap4)) = make_float4(p4.x + p4.y, p5.x + p5.y, p6.x + p6.y, p7.x + p7.y);
            }
        }
        __syncwarp();   // gates for this warp's units are warp-local
        // ===== Warp-local state update (c in registers) =====
        if (doL0) {
            float2 gi = *(const float2*)&sm[SGT0 + gsrc +  0 + pofs];
            float2 gf = *(const float2*)&sm[SGT0 + gsrc +  8 + pofs];
            float2 gz = *(const float2*)&sm[SGT0 + gsrc + 16 + pofs];
            float2 go = *(const float2*)&sm[SGT0 + gsrc + 24 + pofs];
            c0a = fsig(gf.x) * c0a + fsig(gi.x) * ftanh(gz.x);
            c0b = fsig(gf.y) * c0b + fsig(gi.y) * ftanh(gz.y);
            hdst[hoff1]     = fsig(go.x) * ftanh(c0a);
            hdst[hoff1 + 2] = fsig(go.y) * ftanh(c0b);
        }
        if (doL1) {
            float2 gi = *(const float2*)&sm[SGT1 + gsrc +  0 + pofs];
            float2 gf = *(const float2*)&sm[SGT1 + gsrc +  8 + pofs];
            float2 gz = *(const float2*)&sm[SGT1 + gsrc + 16 + pofs];
            float2 go = *(const float2*)&sm[SGT1 + gsrc + 24 + pofs];
            c1a = fsig(gf.x) * c1a + fsig(gi.x) * ftanh(gz.x);
            c1b = fsig(gf.y) * c1b + fsig(gi.y) * ftanh(gz.y);
            hdst[hoff2]     = fsig(go.x) * ftanh(c1a);
            hdst[hoff2 + 2] = fsig(go.y) * ftanh(c1b);
        }
        __syncthreads();   // publish h buf[(s+1)&1] for next iteration
    }

    // ===== Final FC on h2[T-1]: O=1 =====
    // Last h2 write was iter s=512 into buf[(512+1)&1] = buf 1.
    if (tid < 8) {
        float acc = bfc[0];
        #pragma unroll 8
        for (int k = 64; k < 128; ++k)
            acc = fmaf(Wfc[k - 64],
                       sm[SHC + 1024 + (k >> 1) * 16 + tid * 2 + (k & 1)], acc);
        out[b0 + tid] = acc;
    }
}

extern "C" void kernel_launch(void* const* d_in, const int* in_sizes, int n_in,
                              void* d_out, int out_size)
{
    const float* x    = (const float*)d_in[0];
    const float* Wih0 = (const float*)d_in[1];
    const float* Whh0 = (const float*)d_in[2];
    const float* bih0 = (const float*)d_in[3];
    const float* bhh0 = (const float*)d_in[4];
    const float* Wih1 = (const float*)d_in[5];
    const float* Whh1 = (const float*)d_in[6];
    const float* bih1 = (const float*)d_in[7];
    const float* bhh1 = (const float*)d_in[8];
    const float* Wfc  = (const float*)d_in[9];
    const float* bfc  = (const float*)d_in[10];
    float* out = (float*)d_out;

    cudaFuncSetAttribute(lstm2_kernel,
                         cudaFuncAttributeMaxDynamicSharedMemorySize,
                         SMEM_FLOATS * sizeof(float));
    lstm2_kernel<<<128, 256, SMEM_FLOATS * sizeof(float)>>>(
        x, Wih0, Whh0, bih0, bhh0, Wih1, Whh1, bih1, bhh1, Wfc, bfc, out);
}